// round 1
// baseline (speedup 1.0000x reference)
#include <cuda_runtime.h>

#define Bv 4
#define Sv 4096
#define Hv 32
#define Dv 64
#define NSTEPS 128
#define WARPS 32
#define CHUNK (Sv / WARPS)   // 128 rows per warp
#define ROWSTRIDE (Hv * Dv)  // 2048 floats between consecutive s

__device__ __forceinline__ float warp_sum(float v) {
    v += __shfl_xor_sync(0xffffffffu, v, 16);
    v += __shfl_xor_sync(0xffffffffu, v, 8);
    v += __shfl_xor_sync(0xffffffffu, v, 4);
    v += __shfl_xor_sync(0xffffffffu, v, 2);
    v += __shfl_xor_sync(0xffffffffu, v, 1);
    return v;
}

__global__ __launch_bounds__(1024, 1)
void rope_ctx_kernel(const float* __restrict__ q,
                     const float* __restrict__ k,
                     const float* __restrict__ cos_step,
                     const float* __restrict__ sin_step,
                     float* __restrict__ out)
{
    __shared__ float s_cos[NSTEPS];
    __shared__ float s_sin[NSTEPS];
    __shared__ float s_kinv[Sv];          // 16 KB: per-row 1/(||relu(k)||+eps)
    __shared__ float s_agg[WARPS * 64];   // 8 KB: per-chunk kn aggregates

    const int tid  = threadIdx.x;
    const int w    = tid >> 5;
    const int lane = tid & 31;
    const int bh   = blockIdx.x;
    const int b    = bh >> 5;   // H = 32
    const int h    = bh & 31;

    if (tid < NSTEPS) {
        s_cos[tid] = cos_step[tid * Dv];   // cos_step[:, 0]
        s_sin[tid] = sin_step[tid * Dv];
    }

    const size_t base = (size_t)b * Sv * Hv * Dv + (size_t)h * Dv;
    const int s0 = w * CHUNK;

    const float* kp0 = k + base + (size_t)s0 * ROWSTRIDE + lane;

    // ---------------- Phase A: per-chunk kn aggregate + cache kinv ----------
    float cx = 0.f, cy = 0.f;
    {
        const float* kp = kp0;
        #pragma unroll 4
        for (int i = 0; i < CHUNK; ++i) {
            float k0 = __ldg(kp);
            float k1 = __ldg(kp + 32);
            kp += ROWSTRIDE;
            float kr0 = fmaxf(k0, 0.f);
            float kr1 = fmaxf(k1, 0.f);
            float ss = warp_sum(fmaf(kr0, kr0, kr1 * kr1));
            float kinv = 1.0f / (sqrtf(ss) + 1e-6f);
            if (lane == 0) s_kinv[s0 + i] = kinv;
            cx = fmaf(kr0, kinv, cx);
            cy = fmaf(kr1, kinv, cy);
        }
    }
    s_agg[w * 64 + lane]      = cx;
    s_agg[w * 64 + 32 + lane] = cy;
    __syncthreads();

    // Exclusive prefix of chunk aggregates (tiny: <= 31 smem reads per lane)
    float ox = 0.f, oy = 0.f;
    for (int w2 = 0; w2 < w; ++w2) {
        ox += s_agg[w2 * 64 + lane];
        oy += s_agg[w2 * 64 + 32 + lane];
    }

    // ---------------- Phase C: positions + rope + store ---------------------
    const float* kp = kp0;
    const float* qp = q + base + (size_t)s0 * ROWSTRIDE + lane;
    float* qo = out + base + (size_t)s0 * ROWSTRIDE + lane;
    float* ko = qo + (size_t)Bv * Sv * Hv * Dv;

    cx = ox; cy = oy;

    #pragma unroll 2
    for (int i = 0; i < CHUNK; ++i) {
        float k0 = __ldg(kp);
        float k1 = __ldg(kp + 32);
        float q0 = __ldg(qp);
        float q1 = __ldg(qp + 32);

        float kinv = s_kinv[s0 + i];          // broadcast LDS, not loop-carried
        float kr0 = fmaxf(k0, 0.f);
        float kr1 = fmaxf(k1, 0.f);
        cx = fmaf(kr0, kinv, cx);             // inclusive cumsum of kn
        cy = fmaf(kr1, kinv, cy);

        float qr0 = fmaxf(q0, 0.f);
        float qr1 = fmaxf(q1, 0.f);
        float qs = warp_sum(fmaf(qr0, qr0, qr1 * qr1));
        float qinv = 1.0f / (sqrtf(qs) + 1e-6f);

        float dot = warp_sum(fmaf(qr0, cx, qr1 * cy)) * qinv;

        float p = dot * (1.0f / 32.0f);
        p = fminf(fmaxf(p, 0.f), 127.f);
        float pf   = floorf(p);
        int   fi   = (int)pf;
        int   ci   = (int)ceilf(p);
        float frac = p - pf;

        float c0  = s_cos[fi], c1  = s_cos[ci];
        float sn0 = s_sin[fi], sn1 = s_sin[ci];
        float c  = fmaf(frac, c1 - c0, c0);
        float sn = fmaf(frac, sn1 - sn0, sn0);

        // lane owns (d, d+32): rotate_half pair is register-local
        qo[0]  = fmaf(q0, c, -q1 * sn);
        qo[32] = fmaf(q1, c,  q0 * sn);
        ko[0]  = fmaf(k0, c, -k1 * sn);
        ko[32] = fmaf(k1, c,  k0 * sn);

        kp += ROWSTRIDE; qp += ROWSTRIDE; qo += ROWSTRIDE; ko += ROWSTRIDE;
    }
}

extern "C" void kernel_launch(void* const* d_in, const int* in_sizes, int n_in,
                              void* d_out, int out_size)
{
    const float* q        = (const float*)d_in[0];
    const float* k        = (const float*)d_in[1];
    // d_in[2] = v (unused by the reference math)
    const float* cos_step = (const float*)d_in[3];
    const float* sin_step = (const float*)d_in[4];
    // d_in[5] = offset (unused by the reference math)

    rope_ctx_kernel<<<Bv * Hv, 1024>>>(q, k, cos_step, sin_step, (float*)d_out);
}

// round 2
// speedup vs baseline: 1.1740x; 1.1740x over previous
#include <cuda_runtime.h>

#define Bv 4
#define Sv 4096
#define Hv 32
#define Dv 64
#define NSTEPS 128
#define WARPS 32
#define RPW 4                   // rows per warp per tile
#define TILE (WARPS * RPW)      // 128 rows per tile
#define NTILES (Sv / TILE)      // 32 tiles
#define ROWSTRIDE (Hv * Dv)     // 2048 floats between consecutive s

__device__ __forceinline__ float warp_sum(float v) {
    v += __shfl_xor_sync(0xffffffffu, v, 16);
    v += __shfl_xor_sync(0xffffffffu, v, 8);
    v += __shfl_xor_sync(0xffffffffu, v, 4);
    v += __shfl_xor_sync(0xffffffffu, v, 2);
    v += __shfl_xor_sync(0xffffffffu, v, 1);
    return v;
}

__global__ __launch_bounds__(1024, 1)
void rope_ctx_kernel(const float* __restrict__ q,
                     const float* __restrict__ k,
                     const float* __restrict__ cos_step,
                     const float* __restrict__ sin_step,
                     float* __restrict__ out)
{
    __shared__ float s_cos[NSTEPS];
    __shared__ float s_sin[NSTEPS];
    __shared__ float s_agg[2][WARPS][64];   // double-buffered per-tile aggregates

    const int tid  = threadIdx.x;
    const int w    = tid >> 5;
    const int lane = tid & 31;
    const int b    = blockIdx.x >> 5;   // H = 32
    const int h    = blockIdx.x & 31;

    if (tid < NSTEPS) {
        s_cos[tid] = cos_step[tid * Dv];   // cos_step[:, 0]
        s_sin[tid] = sin_step[tid * Dv];
    }
    __syncthreads();

    const size_t base = (size_t)b * Sv * ROWSTRIDE + (size_t)h * Dv;
    const float* kb = k + base + lane;
    const float* qb = q + base + lane;
    float* qo = out + base + lane;
    float* ko = qo + (size_t)Bv * Sv * ROWSTRIDE;

    // running exclusive cumsum base carried across tiles (same in every warp)
    float bx = 0.f, by = 0.f;

    for (int t = 0; t < NTILES; ++t) {
        const int p = t & 1;
        const size_t roff = (size_t)(t * TILE + w * RPW) * ROWSTRIDE;
        const float* kp = kb + roff;

        // ---- load this warp's k rows once; keep in registers --------------
        float k0[RPW], k1[RPW], kn0[RPW], kn1[RPW], ss[RPW];
        #pragma unroll
        for (int i = 0; i < RPW; ++i) {
            k0[i] = __ldg(kp + (size_t)i * ROWSTRIDE);
            k1[i] = __ldg(kp + (size_t)i * ROWSTRIDE + 32);
        }
        #pragma unroll
        for (int i = 0; i < RPW; ++i) {       // 4 independent shuffle chains
            kn0[i] = fmaxf(k0[i], 0.f);
            kn1[i] = fmaxf(k1[i], 0.f);
            ss[i]  = warp_sum(fmaf(kn0[i], kn0[i], kn1[i] * kn1[i]));
        }
        float ax = 0.f, ay = 0.f;
        #pragma unroll
        for (int i = 0; i < RPW; ++i) {
            float kinv = (ss[i] > 0.f)
                       ? __fdividef(1.f, sqrtf(ss[i]) + 1e-6f) : 0.f;
            kn0[i] *= kinv;
            kn1[i] *= kinv;
            ax += kn0[i];
            ay += kn1[i];
        }
        s_agg[p][w][lane]      = ax;
        s_agg[p][w][lane + 32] = ay;
        __syncthreads();

        // ---- cross-warp exclusive prefix + tile total ----------------------
        float ox = bx, oy = by, tx = 0.f, ty = 0.f;
        #pragma unroll 8
        for (int w2 = 0; w2 < WARPS; ++w2) {
            float vx = s_agg[p][w2][lane];
            float vy = s_agg[p][w2][lane + 32];
            if (w2 < w) { ox += vx; oy += vy; }
            tx += vx; ty += vy;
        }
        bx += tx; by += ty;

        // ---- q phase: norms (independent chains) ---------------------------
        const float* qp = qb + roff;
        float q0[RPW], q1[RPW], qinv[RPW];
        #pragma unroll
        for (int i = 0; i < RPW; ++i) {
            q0[i] = __ldg(qp + (size_t)i * ROWSTRIDE);
            q1[i] = __ldg(qp + (size_t)i * ROWSTRIDE + 32);
        }
        #pragma unroll
        for (int i = 0; i < RPW; ++i) {
            float qr0 = fmaxf(q0[i], 0.f);
            float qr1 = fmaxf(q1[i], 0.f);
            float qs  = warp_sum(fmaf(qr0, qr0, qr1 * qr1));
            qinv[i] = (qs > 0.f) ? __fdividef(1.f, sqrtf(qs) + 1e-6f) : 0.f;
        }

        // ---- dots (cum chain is 2 FMAs/row; shuffle chains overlap) + rope --
        float* qoi = qo + roff;
        float* koi = ko + roff;
        #pragma unroll
        for (int i = 0; i < RPW; ++i) {
            ox += kn0[i];                      // inclusive cumsum at this row
            oy += kn1[i];
            float qr0 = fmaxf(q0[i], 0.f);
            float qr1 = fmaxf(q1[i], 0.f);
            float dot = warp_sum(fmaf(qr0, ox, qr1 * oy)) * qinv[i];

            float pcl = fminf(fmaxf(dot * (1.f / 32.f), 0.f), 127.f);
            float pf  = floorf(pcl);
            int   fi  = (int)pf;
            int   ci  = (int)ceilf(pcl);
            float fr  = pcl - pf;

            float c  = fmaf(fr, s_cos[ci] - s_cos[fi], s_cos[fi]);
            float sn = fmaf(fr, s_sin[ci] - s_sin[fi], s_sin[fi]);

            // lane owns (d, d+32): rotate_half pair is register-local
            qoi[(size_t)i * ROWSTRIDE]      = fmaf(q0[i], c, -q1[i] * sn);
            qoi[(size_t)i * ROWSTRIDE + 32] = fmaf(q1[i], c,  q0[i] * sn);
            koi[(size_t)i * ROWSTRIDE]      = fmaf(k0[i], c, -k1[i] * sn);
            koi[(size_t)i * ROWSTRIDE + 32] = fmaf(k1[i], c,  k0[i] * sn);
        }
        // parity double-buffer on s_agg makes one barrier per tile sufficient
    }
}

extern "C" void kernel_launch(void* const* d_in, const int* in_sizes, int n_in,
                              void* d_out, int out_size)
{
    const float* q        = (const float*)d_in[0];
    const float* k        = (const float*)d_in[1];
    // d_in[2] = v (unused by the reference math)
    const float* cos_step = (const float*)d_in[3];
    const float* sin_step = (const float*)d_in[4];
    // d_in[5] = offset (unused by the reference math)

    rope_ctx_kernel<<<Bv * Hv, 1024>>>(q, k, cos_step, sin_step, (float*)d_out);
}

// round 3
// speedup vs baseline: 1.5270x; 1.3007x over previous
#include <cuda_runtime.h>

#define Bv 4
#define Sv 4096
#define Hv 32
#define Dv 64
#define NSTEPS 128
#define WARPS 32
#define ROWSTRIDE (Hv * Dv)     // 2048 floats between consecutive s
#define TILE 128                // rows per tile (4 per warp)
#define NTILES (Sv / TILE)      // 32
#define FULL 0xffffffffu

// sum across the 8 lanes of a row-group (lanes g*8..g*8+7)
__device__ __forceinline__ float grp8_sum(float v) {
    v += __shfl_xor_sync(FULL, v, 4);
    v += __shfl_xor_sync(FULL, v, 2);
    v += __shfl_xor_sync(FULL, v, 1);
    return v;
}

// inclusive scan across the 4 row-groups (stride-8 lanes)
__device__ __forceinline__ float scan_grp(float v, int lane) {
    float t = __shfl_up_sync(FULL, v, 8);
    if (lane >= 8) v += t;
    t = __shfl_up_sync(FULL, v, 16);
    if (lane >= 16) v += t;
    return v;
}

__device__ __forceinline__ float4 relu4(float4 a) {
    return make_float4(fmaxf(a.x, 0.f), fmaxf(a.y, 0.f),
                       fmaxf(a.z, 0.f), fmaxf(a.w, 0.f));
}
__device__ __forceinline__ float dot4(float4 a, float4 b) {
    return fmaf(a.x, b.x, fmaf(a.y, b.y, fmaf(a.z, b.z, a.w * b.w)));
}

__global__ __launch_bounds__(1024, 1)
void rope_ctx_kernel(const float* __restrict__ q,
                     const float* __restrict__ k,
                     const float* __restrict__ cos_step,
                     const float* __restrict__ sin_step,
                     float* __restrict__ out)
{
    __shared__ float2 s_tab[NSTEPS];
    __shared__ float  s_agg[64][33];    // per-dim per-warp tile aggregates
    __shared__ float  s_pref[64][33];   // inclusive cross-warp scan

    const int tid  = threadIdx.x;
    const int w    = tid >> 5;
    const int lane = tid & 31;
    const int g    = lane >> 3;         // row group 0..3
    const int j    = lane & 7;          // dim slot within row
    const int b    = blockIdx.x >> 5;   // H = 32
    const int h    = blockIdx.x & 31;

    if (tid < NSTEPS) {
        s_tab[tid] = make_float2(cos_step[tid * Dv], sin_step[tid * Dv]);
    }
    __syncthreads();

    const size_t base = (size_t)b * Sv * ROWSTRIDE + (size_t)h * Dv;
    const float* qg = q + base;
    const float* kg = k + base;
    float* og = out + base;
    const size_t KOUT = (size_t)Bv * Sv * ROWSTRIDE;

    // carried exclusive cumsum for this lane's 8 dims (replicated across groups)
    float4 basex = make_float4(0.f, 0.f, 0.f, 0.f);
    float4 basey = make_float4(0.f, 0.f, 0.f, 0.f);

    const int dx = 4 * j;          // x dims: dx..dx+3 ; y dims: 32+dx..
    const int dy = 32 + 4 * j;

    for (int t = 0; t < NTILES; ++t) {
        const int row = t * TILE + w * 4 + g;
        const size_t ro = (size_t)row * ROWSTRIDE + dx;

        // ---- load k & q vectors (LDG.128) --------------------------------
        float4 kx = *(const float4*)(kg + ro);
        float4 ky = *(const float4*)(kg + ro + 32);
        float4 qx = *(const float4*)(qg + ro);
        float4 qy = *(const float4*)(qg + ro + 32);

        // ---- k: relu, norm (one 3-shfl reduction serves all 4 rows) -------
        float4 knx = relu4(kx), kny = relu4(ky);
        float ss = grp8_sum(dot4(knx, knx) + dot4(kny, kny));
        float kinv = __fdividef(1.f, sqrtf(ss) + 1e-6f);
        knx.x *= kinv; knx.y *= kinv; knx.z *= kinv; knx.w *= kinv;
        kny.x *= kinv; kny.y *= kinv; kny.z *= kinv; kny.w *= kinv;

        // ---- in-warp inclusive scan across the 4 rows, per component ------
        float4 ix, iy;
        ix.x = scan_grp(knx.x, lane); ix.y = scan_grp(knx.y, lane);
        ix.z = scan_grp(knx.z, lane); ix.w = scan_grp(knx.w, lane);
        iy.x = scan_grp(kny.x, lane); iy.y = scan_grp(kny.y, lane);
        iy.z = scan_grp(kny.z, lane); iy.w = scan_grp(kny.w, lane);

        // group 3 holds the warp's 4-row totals: publish them
        if (g == 3) {
            s_agg[dx    ][w] = ix.x; s_agg[dx + 1][w] = ix.y;
            s_agg[dx + 2][w] = ix.z; s_agg[dx + 3][w] = ix.w;
            s_agg[dy    ][w] = iy.x; s_agg[dy + 1][w] = iy.y;
            s_agg[dy + 2][w] = iy.z; s_agg[dy + 3][w] = iy.w;
        }

        // ---- q: relu + norm (independent; overlaps barrier latency) -------
        float4 qrx = relu4(qx), qry = relu4(qy);
        float qs = grp8_sum(dot4(qrx, qrx) + dot4(qry, qry));
        float qinv = __fdividef(1.f, sqrtf(qs) + 1e-6f);

        __syncthreads();

        // ---- cross-warp scan phase: warp w scans dims {2w, 2w+1} ----------
        #pragma unroll
        for (int dd = 0; dd < 2; ++dd) {
            const int d = 2 * w + dd;
            float v = s_agg[d][lane];
            float u;
            u = __shfl_up_sync(FULL, v, 1);  if (lane >= 1)  v += u;
            u = __shfl_up_sync(FULL, v, 2);  if (lane >= 2)  v += u;
            u = __shfl_up_sync(FULL, v, 4);  if (lane >= 4)  v += u;
            u = __shfl_up_sync(FULL, v, 8);  if (lane >= 8)  v += u;
            u = __shfl_up_sync(FULL, v, 16); if (lane >= 16) v += u;
            s_pref[d][lane] = v;            // inclusive across warps
        }
        __syncthreads();

        // ---- assemble inclusive cum for this row's dims -------------------
        float4 cx, cy;
        if (w > 0) {
            cx.x = basex.x + s_pref[dx    ][w - 1] + ix.x;
            cx.y = basex.y + s_pref[dx + 1][w - 1] + ix.y;
            cx.z = basex.z + s_pref[dx + 2][w - 1] + ix.z;
            cx.w = basex.w + s_pref[dx + 3][w - 1] + ix.w;
            cy.x = basey.x + s_pref[dy    ][w - 1] + iy.x;
            cy.y = basey.y + s_pref[dy + 1][w - 1] + iy.y;
            cy.z = basey.z + s_pref[dy + 2][w - 1] + iy.z;
            cy.w = basey.w + s_pref[dy + 3][w - 1] + iy.w;
        } else {
            cx.x = basex.x + ix.x; cx.y = basex.y + ix.y;
            cx.z = basex.z + ix.z; cx.w = basex.w + ix.w;
            cy.x = basey.x + iy.x; cy.y = basey.y + iy.y;
            cy.z = basey.z + iy.z; cy.w = basey.w + iy.w;
        }
        // advance carried base by the tile grand total
        basex.x += s_pref[dx    ][31]; basex.y += s_pref[dx + 1][31];
        basex.z += s_pref[dx + 2][31]; basex.w += s_pref[dx + 3][31];
        basey.x += s_pref[dy    ][31]; basey.y += s_pref[dy + 1][31];
        basey.z += s_pref[dy + 2][31]; basey.w += s_pref[dy + 3][31];

        // ---- dot, position, rope ------------------------------------------
        float dot = grp8_sum(dot4(qrx, cx) + dot4(qry, cy)) * qinv;

        float p = fminf(fmaxf(dot * (1.f / 32.f), 0.f), 127.f);
        float pf = floorf(p);
        int   fi = (int)pf;
        int   ci = (int)ceilf(p);
        float fr = p - pf;
        float2 t0 = s_tab[fi], t1 = s_tab[ci];
        float cn = fmaf(fr, t1.x - t0.x, t0.x);
        float sn = fmaf(fr, t1.y - t0.y, t0.y);

        float4 oqx, oqy, okx, oky;
        oqx.x = fmaf(qx.x, cn, -qy.x * sn);  oqy.x = fmaf(qy.x, cn, qx.x * sn);
        oqx.y = fmaf(qx.y, cn, -qy.y * sn);  oqy.y = fmaf(qy.y, cn, qx.y * sn);
        oqx.z = fmaf(qx.z, cn, -qy.z * sn);  oqy.z = fmaf(qy.z, cn, qx.z * sn);
        oqx.w = fmaf(qx.w, cn, -qy.w * sn);  oqy.w = fmaf(qy.w, cn, qx.w * sn);
        okx.x = fmaf(kx.x, cn, -ky.x * sn);  oky.x = fmaf(ky.x, cn, kx.x * sn);
        okx.y = fmaf(kx.y, cn, -ky.y * sn);  oky.y = fmaf(ky.y, cn, kx.y * sn);
        okx.z = fmaf(kx.z, cn, -ky.z * sn);  oky.z = fmaf(ky.z, cn, kx.z * sn);
        okx.w = fmaf(kx.w, cn, -ky.w * sn);  oky.w = fmaf(ky.w, cn, kx.w * sn);

        *(float4*)(og + ro)             = oqx;
        *(float4*)(og + ro + 32)        = oqy;
        *(float4*)(og + KOUT + ro)      = okx;
        *(float4*)(og + KOUT + ro + 32) = oky;
        // next tile's s_agg stores are safe: everyone passed the 2nd barrier,
        // and s_pref isn't rewritten until after the next 1st barrier.
    }
}

extern "C" void kernel_launch(void* const* d_in, const int* in_sizes, int n_in,
                              void* d_out, int out_size)
{
    const float* q        = (const float*)d_in[0];
    const float* k        = (const float*)d_in[1];
    // d_in[2] = v (unused by the reference math)
    const float* cos_step = (const float*)d_in[3];
    const float* sin_step = (const float*)d_in[4];
    // d_in[5] = offset (unused by the reference math)

    rope_ctx_kernel<<<Bv * Hv, 1024>>>(q, k, cos_step, sin_step, (float*)d_out);
}

// round 4
// speedup vs baseline: 2.1219x; 1.3896x over previous
#include <cuda_runtime.h>
#include <cstdint>

#define Bv 4
#define Sv 4096
#define Hv 32
#define Dv 64
#define NSTEPS 128
#define WARPS 32
#define ROWSTRIDE (Hv * Dv)       // 2048 floats between consecutive s
#define TILE 128                  // rows per tile (4 per warp)
#define NTILES (Sv / TILE)        // 32
#define TILE_FLOATS (TILE * Dv)   // 8192 floats = 32 KB
#define FULL 0xffffffffu

// sum across the 8 lanes of a row-group (lanes g*8..g*8+7)
__device__ __forceinline__ float grp8_sum(float v) {
    v += __shfl_xor_sync(FULL, v, 4);
    v += __shfl_xor_sync(FULL, v, 2);
    v += __shfl_xor_sync(FULL, v, 1);
    return v;
}

// inclusive scan across the 4 row-groups (stride-8 lanes)
__device__ __forceinline__ float scan_grp(float v, int lane) {
    float t = __shfl_up_sync(FULL, v, 8);
    if (lane >= 8) v += t;
    t = __shfl_up_sync(FULL, v, 16);
    if (lane >= 16) v += t;
    return v;
}

__device__ __forceinline__ float4 relu4(float4 a) {
    return make_float4(fmaxf(a.x, 0.f), fmaxf(a.y, 0.f),
                       fmaxf(a.z, 0.f), fmaxf(a.w, 0.f));
}
__device__ __forceinline__ float dot4(float4 a, float4 b) {
    return fmaf(a.x, b.x, fmaf(a.y, b.y, fmaf(a.z, b.z, a.w * b.w)));
}

__device__ __forceinline__ void cp16(float* dst_smem, const float* src) {
    uint32_t d = (uint32_t)__cvta_generic_to_shared(dst_smem);
    asm volatile("cp.async.cg.shared.global [%0], [%1], 16;"
                 :: "r"(d), "l"(src) : "memory");
}

__global__ __launch_bounds__(1024, 1)
void rope_ctx_kernel(const float* __restrict__ q,
                     const float* __restrict__ k,
                     const float* __restrict__ cos_step,
                     const float* __restrict__ sin_step,
                     float* __restrict__ out)
{
    extern __shared__ float smem[];
    float* sk = smem;                      // [2][TILE][64]
    float* sq = smem + 2 * TILE_FLOATS;    // [2][TILE][64]

    __shared__ float2 s_tab[NSTEPS];
    __shared__ float  s_agg[64][33];       // per-dim per-warp tile aggregates
    __shared__ float  s_pref[64][33];      // inclusive cross-warp scan

    const int tid  = threadIdx.x;
    const int w    = tid >> 5;
    const int lane = tid & 31;
    const int g    = lane >> 3;            // row group 0..3
    const int j    = lane & 7;             // dim slot within row
    const int b    = blockIdx.x >> 5;      // H = 32
    const int h    = blockIdx.x & 31;

    if (tid < NSTEPS) {
        s_tab[tid] = make_float2(cos_step[tid * Dv], sin_step[tid * Dv]);
    }

    const size_t base = (size_t)b * Sv * ROWSTRIDE + (size_t)h * Dv;
    const float* qg = q + base;
    const float* kg = k + base;
    float* og = out + base;
    const size_t KOUT = (size_t)Bv * Sv * ROWSTRIDE;

    // ---- async copy of one tile's q+k into the parity buffer ---------------
    auto issue = [&](int t) {
        if (t < NTILES) {
            const size_t toff = (size_t)t * TILE * ROWSTRIDE;
            float* skb = sk + (t & 1) * TILE_FLOATS;
            float* sqb = sq + (t & 1) * TILE_FLOATS;
            #pragma unroll
            for (int c = tid; c < TILE * 16; c += 1024) {   // 2 iters/thread
                const int row  = c >> 4;
                const int slot = (c & 15) * 4;
                const size_t go = toff + (size_t)row * ROWSTRIDE + slot;
                const int so = row * 64 + slot;
                cp16(skb + so, kg + go);
                cp16(sqb + so, qg + go);
            }
        }
        asm volatile("cp.async.commit_group;" ::: "memory");
    };

    issue(0);
    issue(1);

    // carried exclusive cumsum for this lane's 8 dims (replicated across groups)
    float4 basex = make_float4(0.f, 0.f, 0.f, 0.f);
    float4 basey = make_float4(0.f, 0.f, 0.f, 0.f);

    const int dx = 4 * j;            // x dims: dx..dx+3 ; y dims: 32+dx..
    const int dy = 32 + 4 * j;
    const int r  = w * 4 + g;        // this thread's row within a tile

    for (int t = 0; t < NTILES; ++t) {
        const int p = t & 1;
        asm volatile("cp.async.wait_group 1;" ::: "memory");
        __syncthreads();                         // A: tile t resident+visible

        const float* skb = sk + p * TILE_FLOATS;
        const float* sqb = sq + p * TILE_FLOATS;

        float4 kx = *(const float4*)(skb + r * 64 + dx);
        float4 ky = *(const float4*)(skb + r * 64 + dy);
        float4 qx = *(const float4*)(sqb + r * 64 + dx);
        float4 qy = *(const float4*)(sqb + r * 64 + dy);

        // ---- k: relu, norm (one 3-shfl reduction serves all 4 rows) -------
        float4 knx = relu4(kx), kny = relu4(ky);
        float ss = grp8_sum(dot4(knx, knx) + dot4(kny, kny));
        float kinv = __fdividef(1.f, sqrtf(ss) + 1e-6f);
        knx.x *= kinv; knx.y *= kinv; knx.z *= kinv; knx.w *= kinv;
        kny.x *= kinv; kny.y *= kinv; kny.z *= kinv; kny.w *= kinv;

        // ---- in-warp inclusive scan across the 4 rows, per component ------
        float4 ix, iy;
        ix.x = scan_grp(knx.x, lane); ix.y = scan_grp(knx.y, lane);
        ix.z = scan_grp(knx.z, lane); ix.w = scan_grp(knx.w, lane);
        iy.x = scan_grp(kny.x, lane); iy.y = scan_grp(kny.y, lane);
        iy.z = scan_grp(kny.z, lane); iy.w = scan_grp(kny.w, lane);

        // group 3 holds the warp's 4-row totals: publish them
        if (g == 3) {
            s_agg[dx    ][w] = ix.x; s_agg[dx + 1][w] = ix.y;
            s_agg[dx + 2][w] = ix.z; s_agg[dx + 3][w] = ix.w;
            s_agg[dy    ][w] = iy.x; s_agg[dy + 1][w] = iy.y;
            s_agg[dy + 2][w] = iy.z; s_agg[dy + 3][w] = iy.w;
        }

        // ---- q: relu + norm (independent; overlaps) ------------------------
        float4 qrx = relu4(qx), qry = relu4(qy);
        float qs = grp8_sum(dot4(qrx, qrx) + dot4(qry, qry));
        float qinv = __fdividef(1.f, sqrtf(qs) + 1e-6f);

        __syncthreads();                   // B: s_agg ready; buffer p free

        issue(t + 2);                      // refill freed buffer (async)

        // ---- cross-warp scan phase: warp w scans dims {2w, 2w+1} ----------
        #pragma unroll
        for (int dd = 0; dd < 2; ++dd) {
            const int d = 2 * w + dd;
            float v = s_agg[d][lane];
            float u;
            u = __shfl_up_sync(FULL, v, 1);  if (lane >= 1)  v += u;
            u = __shfl_up_sync(FULL, v, 2);  if (lane >= 2)  v += u;
            u = __shfl_up_sync(FULL, v, 4);  if (lane >= 4)  v += u;
            u = __shfl_up_sync(FULL, v, 8);  if (lane >= 8)  v += u;
            u = __shfl_up_sync(FULL, v, 16); if (lane >= 16) v += u;
            s_pref[d][lane] = v;            // inclusive across warps
        }
        __syncthreads();                   // C: s_pref ready

        // ---- assemble inclusive cum for this row's dims -------------------
        float4 cx, cy;
        if (w > 0) {
            cx.x = basex.x + s_pref[dx    ][w - 1] + ix.x;
            cx.y = basex.y + s_pref[dx + 1][w - 1] + ix.y;
            cx.z = basex.z + s_pref[dx + 2][w - 1] + ix.z;
            cx.w = basex.w + s_pref[dx + 3][w - 1] + ix.w;
            cy.x = basey.x + s_pref[dy    ][w - 1] + iy.x;
            cy.y = basey.y + s_pref[dy + 1][w - 1] + iy.y;
            cy.z = basey.z + s_pref[dy + 2][w - 1] + iy.z;
            cy.w = basey.w + s_pref[dy + 3][w - 1] + iy.w;
        } else {
            cx.x = basex.x + ix.x; cx.y = basex.y + ix.y;
            cx.z = basex.z + ix.z; cx.w = basex.w + ix.w;
            cy.x = basey.x + iy.x; cy.y = basey.y + iy.y;
            cy.z = basey.z + iy.z; cy.w = basey.w + iy.w;
        }
        // advance carried base by the tile grand total
        basex.x += s_pref[dx    ][31]; basex.y += s_pref[dx + 1][31];
        basex.z += s_pref[dx + 2][31]; basex.w += s_pref[dx + 3][31];
        basey.x += s_pref[dy    ][31]; basey.y += s_pref[dy + 1][31];
        basey.z += s_pref[dy + 2][31]; basey.w += s_pref[dy + 3][31];

        // ---- dot, position, rope ------------------------------------------
        float dot = grp8_sum(dot4(qrx, cx) + dot4(qry, cy)) * qinv;

        float pp = fminf(fmaxf(dot * (1.f / 32.f), 0.f), 127.f);
        float pf = floorf(pp);
        int   fi = (int)pf;
        int   ci = (int)ceilf(pp);
        float fr = pp - pf;
        float2 t0 = s_tab[fi], t1 = s_tab[ci];
        float cn = fmaf(fr, t1.x - t0.x, t0.x);
        float sn = fmaf(fr, t1.y - t0.y, t0.y);

        float4 oqx, oqy, okx, oky;
        oqx.x = fmaf(qx.x, cn, -qy.x * sn);  oqy.x = fmaf(qy.x, cn, qx.x * sn);
        oqx.y = fmaf(qx.y, cn, -qy.y * sn);  oqy.y = fmaf(qy.y, cn, qx.y * sn);
        oqx.z = fmaf(qx.z, cn, -qy.z * sn);  oqy.z = fmaf(qy.z, cn, qx.z * sn);
        oqx.w = fmaf(qx.w, cn, -qy.w * sn);  oqy.w = fmaf(qy.w, cn, qx.w * sn);
        okx.x = fmaf(kx.x, cn, -ky.x * sn);  oky.x = fmaf(ky.x, cn, kx.x * sn);
        okx.y = fmaf(kx.y, cn, -ky.y * sn);  oky.y = fmaf(ky.y, cn, kx.y * sn);
        okx.z = fmaf(kx.z, cn, -ky.z * sn);  oky.z = fmaf(ky.z, cn, kx.z * sn);
        okx.w = fmaf(kx.w, cn, -ky.w * sn);  oky.w = fmaf(ky.w, cn, kx.w * sn);

        const size_t ro = (size_t)(t * TILE + r) * ROWSTRIDE + dx;
        *(float4*)(og + ro)             = oqx;
        *(float4*)(og + ro + 32)        = oqy;
        *(float4*)(og + KOUT + ro)      = okx;
        *(float4*)(og + KOUT + ro + 32) = oky;
    }
}

extern "C" void kernel_launch(void* const* d_in, const int* in_sizes, int n_in,
                              void* d_out, int out_size)
{
    const float* q        = (const float*)d_in[0];
    const float* k        = (const float*)d_in[1];
    // d_in[2] = v (unused by the reference math)
    const float* cos_step = (const float*)d_in[3];
    const float* sin_step = (const float*)d_in[4];
    // d_in[5] = offset (unused by the reference math)

    const size_t dyn = (size_t)4 * TILE_FLOATS * sizeof(float);  // 128 KB
    cudaFuncSetAttribute(rope_ctx_kernel,
                         cudaFuncAttributeMaxDynamicSharedMemorySize, (int)dyn);
    rope_ctx_kernel<<<Bv * Hv, 1024, dyn>>>(q, k, cos_step, sin_step,
                                            (float*)d_out);
}

// round 5
// speedup vs baseline: 2.2246x; 1.0484x over previous
#include <cuda_runtime.h>
#include <cstdint>

#define Bv 4
#define Sv 4096
#define Hv 32
#define Dv 64
#define NSTEPS 128
#define WARPS 32
#define ROWSTRIDE (Hv * Dv)       // 2048 floats between consecutive s
#define TILE 128                  // rows per tile (4 per warp)
#define NTILES (Sv / TILE)        // 32
#define TILE_FLOATS (TILE * Dv)   // 8192 floats = 32 KB
#define NBUF 3
#define FULL 0xffffffffu

// sum across the 8 lanes of a row-group (lanes g*8..g*8+7)
__device__ __forceinline__ float grp8_sum(float v) {
    v += __shfl_xor_sync(FULL, v, 4);
    v += __shfl_xor_sync(FULL, v, 2);
    v += __shfl_xor_sync(FULL, v, 1);
    return v;
}

// inclusive scan across the 4 row-groups (stride-8 lanes)
__device__ __forceinline__ float scan_grp(float v, int lane) {
    float t = __shfl_up_sync(FULL, v, 8);
    if (lane >= 8) v += t;
    t = __shfl_up_sync(FULL, v, 16);
    if (lane >= 16) v += t;
    return v;
}

__device__ __forceinline__ float4 relu4(float4 a) {
    return make_float4(fmaxf(a.x, 0.f), fmaxf(a.y, 0.f),
                       fmaxf(a.z, 0.f), fmaxf(a.w, 0.f));
}
__device__ __forceinline__ float dot4(float4 a, float4 b) {
    return fmaf(a.x, b.x, fmaf(a.y, b.y, fmaf(a.z, b.z, a.w * b.w)));
}

__device__ __forceinline__ void cp16(float* dst_smem, const float* src) {
    uint32_t d = (uint32_t)__cvta_generic_to_shared(dst_smem);
    asm volatile("cp.async.cg.shared.global [%0], [%1], 16;"
                 :: "r"(d), "l"(src) : "memory");
}

__global__ __launch_bounds__(1024, 1)
void rope_ctx_kernel(const float* __restrict__ q,
                     const float* __restrict__ k,
                     const float* __restrict__ cos_step,
                     const float* __restrict__ sin_step,
                     float* __restrict__ out)
{
    extern __shared__ float smem[];
    float* sk = smem;                         // [NBUF][TILE][64]
    float* sq = smem + NBUF * TILE_FLOATS;    // [NBUF][TILE][64]

    __shared__ float2 s_tab[NSTEPS];
    __shared__ float  s_agg[64][33];          // per-dim per-warp tile aggregates
    __shared__ float  s_pref[64][33];         // [d][w+1] inclusive; [d][0] = 0

    const int tid  = threadIdx.x;
    const int w    = tid >> 5;
    const int lane = tid & 31;
    const int g    = lane >> 3;               // row group 0..3
    const int j    = lane & 7;                // dim slot within row
    const int b    = blockIdx.x >> 5;         // H = 32
    const int h    = blockIdx.x & 31;

    if (tid < NSTEPS) {
        s_tab[tid] = make_float2(cos_step[tid * Dv], sin_step[tid * Dv]);
    }

    const size_t base = (size_t)b * Sv * ROWSTRIDE + (size_t)h * Dv;
    const float* qg = q + base;
    const float* kg = k + base;
    float* og = out + base;
    const size_t KOUT = (size_t)Bv * Sv * ROWSTRIDE;

    const int dx = 4 * j;              // x dims: dx..dx+3 ; y dims: 32+dx..
    const int dy = 32 + 4 * j;
    const int r  = w * 4 + g;          // this thread's row within a tile
    const int so = r * 64;             // thread's smem row base

    // per-thread-exact staging: this thread copies ONLY the words it reads,
    // so cp.async.wait_group alone (no barrier) makes them visible to it.
    auto issue = [&](int t) {
        if (t < NTILES) {
            const int p = t % NBUF;
            float* skb = sk + p * TILE_FLOATS;
            float* sqb = sq + p * TILE_FLOATS;
            const size_t go = (size_t)(t * TILE + r) * ROWSTRIDE;
            cp16(skb + so + dx, kg + go + dx);
            cp16(skb + so + dy, kg + go + dy);
            cp16(sqb + so + dx, qg + go + dx);
            cp16(sqb + so + dy, qg + go + dy);
        }
        asm volatile("cp.async.commit_group;" ::: "memory");
    };

    issue(0);
    issue(1);

    // carried exclusive cumsum for this lane's 8 dims (replicated across groups)
    float4 basex = make_float4(0.f, 0.f, 0.f, 0.f);
    float4 basey = make_float4(0.f, 0.f, 0.f, 0.f);

    for (int t = 0; t < NTILES; ++t) {
        const int p = t % NBUF;
        // group t done (pending: t+1). Then prefetch t+2 into a free buffer.
        asm volatile("cp.async.wait_group 1;" ::: "memory");
        issue(t + 2);

        const float* skb = sk + p * TILE_FLOATS;
        const float* sqb = sq + p * TILE_FLOATS;
        float4 kx = *(const float4*)(skb + so + dx);
        float4 ky = *(const float4*)(skb + so + dy);
        float4 qx = *(const float4*)(sqb + so + dx);
        float4 qy = *(const float4*)(sqb + so + dy);

        // ---- k: relu, norm (one 3-shfl reduction serves all 4 rows) -------
        float4 knx = relu4(kx), kny = relu4(ky);
        float ss = grp8_sum(dot4(knx, knx) + dot4(kny, kny));
        float kinv = __fdividef(1.f, sqrtf(ss) + 1e-6f);
        knx.x *= kinv; knx.y *= kinv; knx.z *= kinv; knx.w *= kinv;
        kny.x *= kinv; kny.y *= kinv; kny.z *= kinv; kny.w *= kinv;

        // ---- in-warp inclusive scan across the 4 rows, per component ------
        float4 ix, iy;
        ix.x = scan_grp(knx.x, lane); ix.y = scan_grp(knx.y, lane);
        ix.z = scan_grp(knx.z, lane); ix.w = scan_grp(knx.w, lane);
        iy.x = scan_grp(kny.x, lane); iy.y = scan_grp(kny.y, lane);
        iy.z = scan_grp(kny.z, lane); iy.w = scan_grp(kny.w, lane);

        // group 3 holds the warp's 4-row totals: publish them
        if (g == 3) {
            s_agg[dx    ][w] = ix.x; s_agg[dx + 1][w] = ix.y;
            s_agg[dx + 2][w] = ix.z; s_agg[dx + 3][w] = ix.w;
            s_agg[dy    ][w] = iy.x; s_agg[dy + 1][w] = iy.y;
            s_agg[dy + 2][w] = iy.z; s_agg[dy + 3][w] = iy.w;
        }

        // ---- q: relu + norm (independent; overlaps barrier arrival) --------
        float4 qrx = relu4(qx), qry = relu4(qy);
        float qs = grp8_sum(dot4(qrx, qrx) + dot4(qry, qry));
        float qinv = __fdividef(1.f, sqrtf(qs) + 1e-6f);

        __syncthreads();                   // B: s_agg ready

        // ---- cross-warp scan phase: warp w scans dims {2w, 2w+1} ----------
        #pragma unroll
        for (int dd = 0; dd < 2; ++dd) {
            const int d = 2 * w + dd;
            float v = s_agg[d][lane];
            float u;
            u = __shfl_up_sync(FULL, v, 1);  if (lane >= 1)  v += u;
            u = __shfl_up_sync(FULL, v, 2);  if (lane >= 2)  v += u;
            u = __shfl_up_sync(FULL, v, 4);  if (lane >= 4)  v += u;
            u = __shfl_up_sync(FULL, v, 8);  if (lane >= 8)  v += u;
            u = __shfl_up_sync(FULL, v, 16); if (lane >= 16) v += u;
            s_pref[d][lane + 1] = v;        // inclusive, shifted by one
            if (lane == 0) s_pref[d][0] = 0.f;
        }
        __syncthreads();                   // C: s_pref ready

        // ---- assemble inclusive cum for this row's dims (branch-free) -----
        float4 cx, cy;
        cx.x = basex.x + s_pref[dx    ][w] + ix.x;
        cx.y = basex.y + s_pref[dx + 1][w] + ix.y;
        cx.z = basex.z + s_pref[dx + 2][w] + ix.z;
        cx.w = basex.w + s_pref[dx + 3][w] + ix.w;
        cy.x = basey.x + s_pref[dy    ][w] + iy.x;
        cy.y = basey.y + s_pref[dy + 1][w] + iy.y;
        cy.z = basey.z + s_pref[dy + 2][w] + iy.z;
        cy.w = basey.w + s_pref[dy + 3][w] + iy.w;

        // advance carried base by the tile grand total
        basex.x += s_pref[dx    ][32]; basex.y += s_pref[dx + 1][32];
        basex.z += s_pref[dx + 2][32]; basex.w += s_pref[dx + 3][32];
        basey.x += s_pref[dy    ][32]; basey.y += s_pref[dy + 1][32];
        basey.z += s_pref[dy + 2][32]; basey.w += s_pref[dy + 3][32];

        // ---- dot, position, rope ------------------------------------------
        float dot = grp8_sum(dot4(qrx, cx) + dot4(qry, cy)) * qinv;

        float pp = fminf(fmaxf(dot * (1.f / 32.f), 0.f), 127.f);
        float pf = floorf(pp);
        int   fi = (int)pf;
        int   ci = (int)ceilf(pp);
        float fr = pp - pf;
        float2 t0 = s_tab[fi], t1 = s_tab[ci];
        float cn = fmaf(fr, t1.x - t0.x, t0.x);
        float sn = fmaf(fr, t1.y - t0.y, t0.y);

        float4 oqx, oqy, okx, oky;
        oqx.x = fmaf(qx.x, cn, -qy.x * sn);  oqy.x = fmaf(qy.x, cn, qx.x * sn);
        oqx.y = fmaf(qx.y, cn, -qy.y * sn);  oqy.y = fmaf(qy.y, cn, qx.y * sn);
        oqx.z = fmaf(qx.z, cn, -qy.z * sn);  oqy.z = fmaf(qy.z, cn, qx.z * sn);
        oqx.w = fmaf(qx.w, cn, -qy.w * sn);  oqy.w = fmaf(qy.w, cn, qx.w * sn);
        okx.x = fmaf(kx.x, cn, -ky.x * sn);  oky.x = fmaf(ky.x, cn, kx.x * sn);
        okx.y = fmaf(kx.y, cn, -ky.y * sn);  oky.y = fmaf(ky.y, cn, kx.y * sn);
        okx.z = fmaf(kx.z, cn, -ky.z * sn);  oky.z = fmaf(ky.z, cn, kx.z * sn);
        okx.w = fmaf(kx.w, cn, -ky.w * sn);  oky.w = fmaf(ky.w, cn, kx.w * sn);

        const size_t ro = (size_t)(t * TILE + r) * ROWSTRIDE + dx;
        *(float4*)(og + ro)             = oqx;
        *(float4*)(og + ro + 32)        = oqy;
        *(float4*)(og + KOUT + ro)      = okx;
        *(float4*)(og + KOUT + ro + 32) = oky;
    }
}

extern "C" void kernel_launch(void* const* d_in, const int* in_sizes, int n_in,
                              void* d_out, int out_size)
{
    const float* q        = (const float*)d_in[0];
    const float* k        = (const float*)d_in[1];
    // d_in[2] = v (unused by the reference math)
    const float* cos_step = (const float*)d_in[3];
    const float* sin_step = (const float*)d_in[4];
    // d_in[5] = offset (unused by the reference math)

    const size_t dyn = (size_t)2 * NBUF * TILE_FLOATS * sizeof(float); // 192 KB
    cudaFuncSetAttribute(rope_ctx_kernel,
                         cudaFuncAttributeMaxDynamicSharedMemorySize, (int)dyn);
    rope_ctx_kernel<<<Bv * Hv, 1024, dyn>>>(q, k, cos_step, sin_step,
                                            (float*)d_out);
}